// round 3
// baseline (speedup 1.0000x reference)
#include <cuda_runtime.h>
#include <cuda_bf16.h>

// Wav2Frames: out[b, c, f] = x[b, f*WINSTEP + c]
// (conv1d with identity eye(400) kernel, stride 160, VALID padding)
// x: (32, 1, 480000) fp32 -> out: (32, 400, 2998) fp32
//
// R3 changes vs R2:
//  - smem skew phys = j + 2*(j>>6): conflict-free, 8B-aligned LDS.64 on the
//    frame-parallel read side (lane bank starts 10*l mod 32, distinct per phase)
//  - store loop: lane owns frame pair (f0+2l, f0+2l+1); per iteration reads
//    (c, c+1) for both frames via 2x LDS.64, writes rows c and c+1 via
//    2x STG.64. Halves LDS count and removes all bank conflicts.
//  - fill: lane permutation sigma (swap bits 3<->4) keeps STS.64 conflict-free
//    under the new skew; LDG stays float4 + fully coalesced (lane order is
//    irrelevant to coalescing).

#define B       32
#define T       480000
#define WINLEN  400
#define WINSTEP 160
#define NFRAMES 2998                                   // even
#define F_TILE  64
#define NTILES  ((NFRAMES + F_TILE - 1) / F_TILE)      // 47
#define SPAN    ((F_TILE - 1) * WINSTEP + WINLEN)      // 10480 floats
#define SM_SZ   (SPAN + 2 * (SPAN >> 6) + 8)           // skewed size (~43.3 KB)
#define NPAIRS  (WINLEN / 2)                           // 200 c-pairs

__global__ __launch_bounds__(512)
void wav2frames_kernel(const float* __restrict__ x, float* __restrict__ out) {
    __shared__ float sm[SM_SZ];

    const int tile = blockIdx.x;
    const int b    = blockIdx.y;
    const int tid  = threadIdx.x;
    const int lane = tid & 31;
    const int w    = tid >> 5;                         // 16 warps

    const int f0 = tile * F_TILE;
    const int x0 = f0 * WINSTEP;                       // multiple of 4

    // ---- fill: float4 LDG (coalesced) -> skewed smem via 2x STS.64 ----
    // lane permutation: swap bits 3 and 4 so STS banks spread under the skew
    const int sig = (lane & 7) | ((lane & 8) << 1) | ((lane & 16) >> 1);

    const float4* __restrict__ src =
        reinterpret_cast<const float4*>(x + (size_t)b * T + x0);
    const int span  = (x0 + SPAN <= T) ? SPAN : (T - x0);   // multiple of 4
    const int span4 = span >> 2;

    for (int base = w * 32; base < span4; base += 512) {
        const int i4 = base + sig;
        if (i4 < span4) {
            const float4 v = src[i4];
            const int p = (i4 << 2) + 2 * (i4 >> 4);   // phys = j + 2*(j>>6)
            *reinterpret_cast<float2*>(sm + p)     = make_float2(v.x, v.y);
            *reinterpret_cast<float2*>(sm + p + 2) = make_float2(v.z, v.w);
        }
    }
    __syncthreads();

    // ---- store: lane owns frame pair (fp, fp+1); warp steps over c-pairs ----
    const int fp = f0 + 2 * lane;
    if (fp < NFRAMES - 1) {                            // pairs never split
        float* __restrict__ ob = out + (size_t)b * WINLEN * NFRAMES + fp;
        const int jb = 2 * lane * WINSTEP;             // 320 * lane

        #pragma unroll 4
        for (int cp = w; cp < NPAIRS; cp += 16) {      // <= 13 iterations
            const int c  = 2 * cp;
            const int j0 = jb + c;                     // frame fp,  cols c,c+1
            const int j1 = j0 + WINSTEP;               // frame fp+1, cols c,c+1
            const float2 a =
                *reinterpret_cast<const float2*>(sm + j0 + 2 * (j0 >> 6));
            const float2 d =
                *reinterpret_cast<const float2*>(sm + j1 + 2 * (j1 >> 6));
            // row c   -> frames (fp, fp+1); row c+1 -> frames (fp, fp+1)
            *reinterpret_cast<float2*>(ob + (size_t)c * NFRAMES) =
                make_float2(a.x, d.x);
            *reinterpret_cast<float2*>(ob + (size_t)(c + 1) * NFRAMES) =
                make_float2(a.y, d.y);
        }
    }
}

extern "C" void kernel_launch(void* const* d_in, const int* in_sizes, int n_in,
                              void* d_out, int out_size) {
    const float* x = (const float*)d_in[0];            // (32, 1, 480000) fp32
    // d_in[1] = W (identity, unused), d_in[2] = winstep (fixed 160, unused)
    float* out = (float*)d_out;                        // (32, 400, 2998) fp32

    dim3 grid(NTILES, B);                              // 47 x 32 = 1504 CTAs
    wav2frames_kernel<<<grid, 512>>>(x, out);
}